// round 7
// baseline (speedup 1.0000x reference)
#include <cuda_runtime.h>
#include <cuda_bf16.h>
#include <math_constants.h>

typedef __nv_bfloat16 bf16;
typedef unsigned int u32;

#define GVQ_M 32768   // B*T
#define GVQ_D 1024
#define GVQ_V 1024

// ---------------------------------------------------------------------------
// Scratch (device globals — no allocations allowed anywhere)
// ---------------------------------------------------------------------------
__device__ bf16 g_Xhi[(size_t)GVQ_M * GVQ_D];
__device__ bf16 g_Xlo[(size_t)GVQ_M * GVQ_D];
__device__ bf16 g_Shi[(size_t)GVQ_M * GVQ_V];
__device__ bf16 g_Slo[(size_t)GVQ_M * GVQ_V];
__device__ bf16 g_Chi[(size_t)GVQ_V * GVQ_D];   // codebook [V,D]  (K-major, GEMM1 B)
__device__ bf16 g_Clo[(size_t)GVQ_V * GVQ_D];
__device__ bf16 g_CThi[(size_t)GVQ_D * GVQ_V];  // codebook^T [D,V] (K-major, GEMM2 B)
__device__ bf16 g_CTlo[(size_t)GVQ_D * GVQ_V];

// ---------------------------------------------------------------------------
// helpers
// ---------------------------------------------------------------------------
__device__ __forceinline__ u32 smem_u32(const void* p) {
    u32 a;
    asm("{ .reg .u64 t; cvta.to.shared.u64 t, %1; cvt.u32.u64 %0, t; }" : "=r"(a) : "l"(p));
    return a;
}
__device__ __forceinline__ void cpa16(u32 dst, const void* src) {
    asm volatile("cp.async.cg.shared.global [%0], [%1], 16;" :: "r"(dst), "l"(src) : "memory");
}
__device__ __forceinline__ void cp_commit() {
    asm volatile("cp.async.commit_group;" ::: "memory");
}
__device__ __forceinline__ void ldsm4(u32* r, u32 addr) {
    asm volatile("ldmatrix.sync.aligned.m8n8.x4.shared.b16 {%0,%1,%2,%3}, [%4];"
                 : "=r"(r[0]), "=r"(r[1]), "=r"(r[2]), "=r"(r[3]) : "r"(addr));
}
__device__ __forceinline__ void mma_bf16(float* c, const u32* a, const u32* b) {
    asm volatile("mma.sync.aligned.m16n8k16.row.col.f32.bf16.bf16.f32 "
                 "{%0,%1,%2,%3}, {%4,%5,%6,%7}, {%8,%9}, {%0,%1,%2,%3};"
                 : "+f"(c[0]), "+f"(c[1]), "+f"(c[2]), "+f"(c[3])
                 : "r"(a[0]), "r"(a[1]), "r"(a[2]), "r"(a[3]), "r"(b[0]), "r"(b[1]));
}
__device__ __forceinline__ void split2(float x, bf16& h, bf16& l) {
    h = __float2bfloat16(x);
    l = __float2bfloat16(x - __bfloat162float(h));
}
// smem tile: rows x 32 bf16 (64B rows, 4x16B chunks), XOR swizzle on chunk
__device__ __forceinline__ u32 tile_off(int row, int chunk) {
    return (u32)(row * 64 + ((chunk ^ ((row >> 1) & 3)) << 4));
}

// ---------------------------------------------------------------------------
// HMMA split-bf16 GEMM: Cout[M,1024] = (Ahi+Alo) @ (Bhi+Blo)^T  (3-term)
// CTA 128x128, 8 warps (warp tile 64x32: 2 M x 4 N), BK=32, 3-stage pipeline,
// 96 KB smem, 2 CTAs/SM -> 4 warps/SMSP (probe for HMMA rt=4 vs rt=8).
// ---------------------------------------------------------------------------
#define BK 32
#define NSTAGES 3
#define TILE_B 8192                 // 128 rows * 64B (per operand per hi/lo)
#define STAGE_B (4 * TILE_B)        // Ah, Al, Bh, Bl = 32 KB
#define GVQ_SMEM (NSTAGES * STAGE_B)  // 98304
#define NITERS (1024 / BK)          // 32

__device__ __forceinline__ void load_stage(u32 sbase,
                                           const bf16* __restrict__ Ahi, const bf16* __restrict__ Alo,
                                           const bf16* __restrict__ Bhi, const bf16* __restrict__ Blo,
                                           int row0, int col0, int k0, int tid) {
#pragma unroll
    for (int q = 0; q < 2; ++q) {
        int idx = tid + q * 256;            // 0..511
        int r = idx >> 2;                   // row 0..127
        int c = idx & 3;                    // 16B chunk
        u32 off = tile_off(r, c);
        const size_t ga = (size_t)(row0 + r) * 1024 + k0 + c * 8;
        const size_t gb = (size_t)(col0 + r) * 1024 + k0 + c * 8;
        cpa16(sbase + off,              Ahi + ga);
        cpa16(sbase + TILE_B + off,     Alo + ga);
        cpa16(sbase + 2 * TILE_B + off, Bhi + gb);
        cpa16(sbase + 3 * TILE_B + off, Blo + gb);
    }
}

__global__ __launch_bounds__(256, 2)
void gvq_mma_gemm(const bf16* __restrict__ Ahi, const bf16* __restrict__ Alo,
                  const bf16* __restrict__ Bhi, const bf16* __restrict__ Blo,
                  float* __restrict__ Cout)
{
    extern __shared__ char dsm[];
    const u32 sm = smem_u32(dsm);

    const int tid  = threadIdx.x;
    const int wid  = tid >> 5;
    const int lane = tid & 31;
    const int row0 = blockIdx.y * 128;
    const int col0 = blockIdx.x * 128;
    const int wm = (wid & 1) * 64;          // 2 warps along M
    const int wn = (wid >> 1) * 32;         // 4 warps along N

    // ldmatrix per-lane row / chunk-select (A and B differ)
    const int rowA = wm + (lane & 7) + ((lane >> 3) & 1) * 8;
    const int selA = (lane >> 4) & 1;       // k-lo / k-hi 16B
    const int rowB = wn + (lane & 7) + ((lane >> 4) & 1) * 8;
    const int selB = (lane >> 3) & 1;

    float acc[4][4][4];                     // 4 m16 x 4 n8
#pragma unroll
    for (int i = 0; i < 4; ++i)
#pragma unroll
        for (int j = 0; j < 4; ++j)
#pragma unroll
            for (int q = 0; q < 4; ++q) acc[i][j][q] = 0.0f;

    // prologue: stages 0..1
#pragma unroll
    for (int s = 0; s < NSTAGES - 1; ++s) {
        load_stage(sm + s * STAGE_B, Ahi, Alo, Bhi, Blo, row0, col0, s * BK, tid);
        cp_commit();
    }

    for (int it = 0; it < NITERS; ++it) {
        asm volatile("cp.async.wait_group %0;" :: "n"(NSTAGES - 2) : "memory");
        __syncthreads();

        const int nx = it + NSTAGES - 1;
        if (nx < NITERS)
            load_stage(sm + (nx % NSTAGES) * STAGE_B, Ahi, Alo, Bhi, Blo,
                       row0, col0, nx * BK, tid);
        cp_commit();

        const u32 sb  = sm + (it % NSTAGES) * STAGE_B;
        const u32 sbB = sb + 2 * TILE_B;
#pragma unroll
        for (int s = 0; s < 2; ++s) {       // two k16 steps per BK=32
            // --- load ah + bh, do hi*hi ---
            u32 ah[4][4];
#pragma unroll
            for (int mt = 0; mt < 4; ++mt)
                ldsm4(ah[mt], sb + tile_off(rowA + mt * 16, 2 * s + selA));
            u32 bh[2][4];
#pragma unroll
            for (int g = 0; g < 2; ++g)
                ldsm4(bh[g], sbB + tile_off(rowB + g * 16, 2 * s + selB));
#pragma unroll
            for (int mt = 0; mt < 4; ++mt)
#pragma unroll
                for (int nt = 0; nt < 4; ++nt)
                    mma_bf16(acc[mt][nt], ah[mt], &bh[nt >> 1][(nt & 1) * 2]);
            // --- load al, do lo*hi (al dies after) ---
            {
                u32 al[4][4];
#pragma unroll
                for (int mt = 0; mt < 4; ++mt)
                    ldsm4(al[mt], sb + TILE_B + tile_off(rowA + mt * 16, 2 * s + selA));
#pragma unroll
                for (int mt = 0; mt < 4; ++mt)
#pragma unroll
                    for (int nt = 0; nt < 4; ++nt)
                        mma_bf16(acc[mt][nt], al[mt], &bh[nt >> 1][(nt & 1) * 2]);
            }
            // --- load bl, do hi*lo ---
            {
                u32 bl[2][4];
#pragma unroll
                for (int g = 0; g < 2; ++g)
                    ldsm4(bl[g], sbB + TILE_B + tile_off(rowB + g * 16, 2 * s + selB));
#pragma unroll
                for (int mt = 0; mt < 4; ++mt)
#pragma unroll
                    for (int nt = 0; nt < 4; ++nt)
                        mma_bf16(acc[mt][nt], ah[mt], &bl[nt >> 1][(nt & 1) * 2]);
            }
        }
        __syncthreads();
    }

    // epilogue: direct fp32 stores
#pragma unroll
    for (int mt = 0; mt < 4; ++mt) {
        const int r0 = row0 + wm + mt * 16 + (lane >> 2);
#pragma unroll
        for (int nt = 0; nt < 4; ++nt) {
            const int cc = col0 + wn + nt * 8 + (lane & 3) * 2;
            float* o0 = Cout + (size_t)r0 * 1024 + cc;
            float* o1 = Cout + (size_t)(r0 + 8) * 1024 + cc;
            o0[0] = acc[mt][nt][0]; o0[1] = acc[mt][nt][1];
            o1[0] = acc[mt][nt][2]; o1[1] = acc[mt][nt][3];
        }
    }
}

// ---------------------------------------------------------------------------
// Prep: split X into bf16 hi/lo
// ---------------------------------------------------------------------------
__global__ __launch_bounds__(256)
void gvq_split_kernel(const float* __restrict__ X, bf16* __restrict__ hi, bf16* __restrict__ lo)
{
    size_t i = (size_t)blockIdx.x * 256 + threadIdx.x;   // float4 index
    float4 v = reinterpret_cast<const float4*>(X)[i];
    bf16 h0, h1, h2, h3, l0, l1, l2, l3;
    split2(v.x, h0, l0); split2(v.y, h1, l1); split2(v.z, h2, l2); split2(v.w, h3, l3);
    __nv_bfloat162* H = reinterpret_cast<__nv_bfloat162*>(hi);
    __nv_bfloat162* L = reinterpret_cast<__nv_bfloat162*>(lo);
    H[2 * i]     = __nv_bfloat162(h0, h1);
    H[2 * i + 1] = __nv_bfloat162(h2, h3);
    L[2 * i]     = __nv_bfloat162(l0, l1);
    L[2 * i + 1] = __nv_bfloat162(l2, l3);
}

// ---------------------------------------------------------------------------
// Prep: split codebook (straight) + split transposed codebook
// ---------------------------------------------------------------------------
__global__ __launch_bounds__(256)
void gvq_splitC_kernel(const float* __restrict__ C)
{
    __shared__ float t[32][33];
    const int tx = threadIdx.x, ty = threadIdx.y;   // 32 x 8
    const int x = blockIdx.x * 32 + tx;
#pragma unroll
    for (int j = 0; j < 4; ++j) {
        int y = blockIdx.y * 32 + ty + j * 8;
        float v = C[(size_t)y * GVQ_D + x];
        t[ty + j * 8][tx] = v;
        bf16 h, l; split2(v, h, l);
        g_Chi[(size_t)y * GVQ_D + x] = h;
        g_Clo[(size_t)y * GVQ_D + x] = l;
    }
    __syncthreads();
    const int x2 = blockIdx.y * 32 + tx;
#pragma unroll
    for (int j = 0; j < 4; ++j) {
        int y2 = blockIdx.x * 32 + ty + j * 8;
        float v = t[tx][ty + j * 8];
        bf16 h, l; split2(v, h, l);
        g_CThi[(size_t)y2 * GVQ_V + x2] = h;
        g_CTlo[(size_t)y2 * GVQ_V + x2] = l;
    }
}

// ---------------------------------------------------------------------------
// Gumbel + softmax (in place) with fast intrinsics; emits bf16 hi/lo split too
// ---------------------------------------------------------------------------
__global__ __launch_bounds__(256)
void gvq_gumbel_softmax_kernel(float* __restrict__ S, const float* __restrict__ U,
                               bf16* __restrict__ Shi, bf16* __restrict__ Slo)
{
    const int row = blockIdx.x;
    float* s       = S + (size_t)row * GVQ_V;
    const float* u = U + (size_t)row * GVQ_V;
    const int tid  = threadIdx.x;
    const int lane = tid & 31;
    const int wid  = tid >> 5;

    __shared__ float red[8];
    __shared__ float stat;

    float z[4];
    float m = -CUDART_INF_F;
#pragma unroll
    for (int i = 0; i < 4; ++i) {
        int idx = tid + i * 256;
        float uu = u[idx];
        float g  = -__logf(-__logf(uu + 1e-20f) + 1e-20f);
        float zz = (s[idx] + g) * 2.0f;   // 1/TEMPERATURE
        z[i] = zz;
        m = fmaxf(m, zz);
    }
#pragma unroll
    for (int o = 16; o > 0; o >>= 1)
        m = fmaxf(m, __shfl_xor_sync(0xffffffffu, m, o));
    if (lane == 0) red[wid] = m;
    __syncthreads();
    if (tid == 0) {
        float mm = red[0];
#pragma unroll
        for (int i = 1; i < 8; ++i) mm = fmaxf(mm, red[i]);
        stat = mm;
    }
    __syncthreads();
    m = stat;

    float lsum = 0.0f;
#pragma unroll
    for (int i = 0; i < 4; ++i) {
        z[i] = __expf(z[i] - m);
        lsum += z[i];
    }
#pragma unroll
    for (int o = 16; o > 0; o >>= 1)
        lsum += __shfl_xor_sync(0xffffffffu, lsum, o);
    __syncthreads();
    if (lane == 0) red[wid] = lsum;
    __syncthreads();
    if (tid == 0) {
        float tsum = 0.0f;
#pragma unroll
        for (int i = 0; i < 8; ++i) tsum += red[i];
        stat = tsum;
    }
    __syncthreads();
    const float inv = 1.0f / stat;

#pragma unroll
    for (int i = 0; i < 4; ++i) {
        int idx = tid + i * 256;
        float p = z[i] * inv;
        s[idx] = p;
        bf16 h, l; split2(p, h, l);
        Shi[(size_t)row * GVQ_V + idx] = h;
        Slo[(size_t)row * GVQ_V + idx] = l;
    }
}

// ---------------------------------------------------------------------------
// kernel_launch
// ---------------------------------------------------------------------------
extern "C" void kernel_launch(void* const* d_in, const int* in_sizes, int n_in,
                              void* d_out, int out_size)
{
    (void)in_sizes; (void)n_in; (void)out_size;
    const float* X = (const float*)d_in[0];
    const float* C = (const float*)d_in[1];
    const float* U = (const float*)d_in[2];

    float* quant = (float*)d_out;                           // B*T*D
    float* soft  = (float*)d_out + (size_t)GVQ_M * GVQ_D;   // B*T*V

    void *pXhi, *pXlo, *pShi, *pSlo, *pChi, *pClo, *pCThi, *pCTlo;
    cudaGetSymbolAddress(&pXhi, g_Xhi);   cudaGetSymbolAddress(&pXlo, g_Xlo);
    cudaGetSymbolAddress(&pShi, g_Shi);   cudaGetSymbolAddress(&pSlo, g_Slo);
    cudaGetSymbolAddress(&pChi, g_Chi);   cudaGetSymbolAddress(&pClo, g_Clo);
    cudaGetSymbolAddress(&pCThi, g_CThi); cudaGetSymbolAddress(&pCTlo, g_CTlo);

    cudaFuncSetAttribute(gvq_mma_gemm, cudaFuncAttributeMaxDynamicSharedMemorySize, GVQ_SMEM);

    // 1) split X
    gvq_split_kernel<<<(GVQ_M * GVQ_D) / (256 * 4), 256>>>(X, (bf16*)pXhi, (bf16*)pXlo);
    // 2) split + transpose codebook
    gvq_splitC_kernel<<<dim3(32, 32), dim3(32, 8)>>>(C);
    // 3) logits = X @ C^T  -> soft region (fp32)
    gvq_mma_gemm<<<dim3(GVQ_V / 128, GVQ_M / 128), 256, GVQ_SMEM>>>(
        (const bf16*)pXhi, (const bf16*)pXlo, (const bf16*)pChi, (const bf16*)pClo, soft);
    // 4) gumbel softmax in place + bf16 split of result
    gvq_gumbel_softmax_kernel<<<GVQ_M, 256>>>(soft, U, (bf16*)pShi, (bf16*)pSlo);
    // 5) quantized = soft @ C  (B operand = C^T, K-major) -> quant region
    gvq_mma_gemm<<<dim3(GVQ_D / 128, GVQ_M / 128), 256, GVQ_SMEM>>>(
        (const bf16*)pShi, (const bf16*)pSlo, (const bf16*)pCThi, (const bf16*)pCTlo, quant);
}

// round 8
// speedup vs baseline: 1.1605x; 1.1605x over previous
#include <cuda_runtime.h>
#include <cuda_bf16.h>
#include <math_constants.h>

typedef __nv_bfloat16 bf16;
typedef unsigned int u32;

#define GVQ_M 32768   // B*T
#define GVQ_D 1024
#define GVQ_V 1024

// ---------------------------------------------------------------------------
// Scratch (device globals — no allocations allowed anywhere)
// ---------------------------------------------------------------------------
__device__ bf16 g_Xhi[(size_t)GVQ_M * GVQ_D];
__device__ bf16 g_Xlo[(size_t)GVQ_M * GVQ_D];
__device__ bf16 g_Shi[(size_t)GVQ_M * GVQ_V];
__device__ bf16 g_Slo[(size_t)GVQ_M * GVQ_V];
__device__ bf16 g_Chi[(size_t)GVQ_V * GVQ_D];   // codebook [V,D]  (K-major, GEMM1 B)
__device__ bf16 g_Clo[(size_t)GVQ_V * GVQ_D];
__device__ bf16 g_CThi[(size_t)GVQ_D * GVQ_V];  // codebook^T [D,V] (K-major, GEMM2 B)
__device__ bf16 g_CTlo[(size_t)GVQ_D * GVQ_V];

// ---------------------------------------------------------------------------
// helpers
// ---------------------------------------------------------------------------
__device__ __forceinline__ u32 smem_u32(const void* p) {
    u32 a;
    asm("{ .reg .u64 t; cvta.to.shared.u64 t, %1; cvt.u32.u64 %0, t; }" : "=r"(a) : "l"(p));
    return a;
}
__device__ __forceinline__ void cpa16(u32 dst, const void* src) {
    asm volatile("cp.async.cg.shared.global [%0], [%1], 16;" :: "r"(dst), "l"(src) : "memory");
}
__device__ __forceinline__ void cp_commit() {
    asm volatile("cp.async.commit_group;" ::: "memory");
}
__device__ __forceinline__ void ldsm4(u32* r, u32 addr) {
    asm volatile("ldmatrix.sync.aligned.m8n8.x4.shared.b16 {%0,%1,%2,%3}, [%4];"
                 : "=r"(r[0]), "=r"(r[1]), "=r"(r[2]), "=r"(r[3]) : "r"(addr));
}
__device__ __forceinline__ void mma_bf16(float* c, const u32* a, const u32* b) {
    asm volatile("mma.sync.aligned.m16n8k16.row.col.f32.bf16.bf16.f32 "
                 "{%0,%1,%2,%3}, {%4,%5,%6,%7}, {%8,%9}, {%0,%1,%2,%3};"
                 : "+f"(c[0]), "+f"(c[1]), "+f"(c[2]), "+f"(c[3])
                 : "r"(a[0]), "r"(a[1]), "r"(a[2]), "r"(a[3]), "r"(b[0]), "r"(b[1]));
}
__device__ __forceinline__ void split2(float x, bf16& h, bf16& l) {
    h = __float2bfloat16(x);
    l = __float2bfloat16(x - __bfloat162float(h));
}
// smem tile: rows x 32 bf16 (64B rows, 4x16B chunks), XOR swizzle on chunk
__device__ __forceinline__ u32 tile_off(int row, int chunk) {
    return (u32)(row * 64 + ((chunk ^ ((row >> 1) & 3)) << 4));
}

// ---------------------------------------------------------------------------
// HMMA split-bf16 GEMM: Cout[M,1024] = (Ahi+Alo) @ (Bhi+Blo)^T  (3-term)
// A: [M,1024] K-major bf16, B: [1024 rows, 1024] K-major bf16.
// CTA 128x128, 4 warps (64x64 each), BK=32, 3-stage cp.async pipeline,
// 96 KB smem -> 2 CTAs/SM: barrier stalls of one CTA hidden by the other.
// (Round-6 configuration: measured ~408 us/GEMM = ~88% of HMMA issue floor.)
// ---------------------------------------------------------------------------
#define BK 32
#define NSTAGES 3
#define TILE_B 8192                 // 128 rows * 64B (per operand per hi/lo)
#define STAGE_B (4 * TILE_B)        // Ah, Al, Bh, Bl = 32 KB
#define GVQ_SMEM (NSTAGES * STAGE_B)  // 98304
#define NITERS (1024 / BK)          // 32

__device__ __forceinline__ void load_stage(u32 sbase,
                                           const bf16* __restrict__ Ahi, const bf16* __restrict__ Alo,
                                           const bf16* __restrict__ Bhi, const bf16* __restrict__ Blo,
                                           int row0, int col0, int k0, int tid) {
#pragma unroll
    for (int q = 0; q < 4; ++q) {
        int idx = tid + q * 128;            // 0..511
        int r = idx >> 2;                   // row 0..127
        int c = idx & 3;                    // 16B chunk
        u32 off = tile_off(r, c);
        const size_t ga = (size_t)(row0 + r) * 1024 + k0 + c * 8;
        const size_t gb = (size_t)(col0 + r) * 1024 + k0 + c * 8;
        cpa16(sbase + off,              Ahi + ga);
        cpa16(sbase + TILE_B + off,     Alo + ga);
        cpa16(sbase + 2 * TILE_B + off, Bhi + gb);
        cpa16(sbase + 3 * TILE_B + off, Blo + gb);
    }
}

__global__ __launch_bounds__(128, 2)
void gvq_mma_gemm(const bf16* __restrict__ Ahi, const bf16* __restrict__ Alo,
                  const bf16* __restrict__ Bhi, const bf16* __restrict__ Blo,
                  float* __restrict__ Cout)
{
    extern __shared__ char dsm[];
    const u32 sm = smem_u32(dsm);

    const int tid  = threadIdx.x;
    const int wid  = tid >> 5;
    const int lane = tid & 31;
    const int row0 = blockIdx.y * 128;
    const int col0 = blockIdx.x * 128;
    const int wm = (wid & 1) * 64;          // warp M offset
    const int wn = (wid >> 1) * 64;         // warp N offset

    // ldmatrix per-lane row / chunk-select (A and B differ)
    const int rowA = wm + (lane & 7) + ((lane >> 3) & 1) * 8;
    const int selA = (lane >> 4) & 1;       // k-lo / k-hi 16B
    const int rowB = wn + (lane & 7) + ((lane >> 4) & 1) * 8;
    const int selB = (lane >> 3) & 1;

    float acc[4][8][4];
#pragma unroll
    for (int i = 0; i < 4; ++i)
#pragma unroll
        for (int j = 0; j < 8; ++j)
#pragma unroll
            for (int q = 0; q < 4; ++q) acc[i][j][q] = 0.0f;

    // prologue: stages 0..1
#pragma unroll
    for (int s = 0; s < NSTAGES - 1; ++s) {
        load_stage(sm + s * STAGE_B, Ahi, Alo, Bhi, Blo, row0, col0, s * BK, tid);
        cp_commit();
    }

    for (int it = 0; it < NITERS; ++it) {
        asm volatile("cp.async.wait_group %0;" :: "n"(NSTAGES - 2) : "memory");
        __syncthreads();

        // issue next stage's loads (empty commit keeps group counting uniform)
        const int nx = it + NSTAGES - 1;
        if (nx < NITERS)
            load_stage(sm + (nx % NSTAGES) * STAGE_B, Ahi, Alo, Bhi, Blo,
                       row0, col0, nx * BK, tid);
        cp_commit();

        const u32 sb  = sm + (it % NSTAGES) * STAGE_B;
        const u32 sbB = sb + 2 * TILE_B;
#pragma unroll
        for (int s = 0; s < 2; ++s) {       // two k16 steps per BK=32
            u32 ah[4][4], al[4][4];
#pragma unroll
            for (int mt = 0; mt < 4; ++mt) {
                u32 off = tile_off(rowA + mt * 16, 2 * s + selA);
                ldsm4(ah[mt], sb + off);
                ldsm4(al[mt], sb + TILE_B + off);
            }
#pragma unroll
            for (int h = 0; h < 2; ++h) {   // n half: 32 cols
                u32 bh[2][4], bl[2][4];
#pragma unroll
                for (int nt2 = 0; nt2 < 2; ++nt2) {
                    u32 off = tile_off(rowB + h * 32 + nt2 * 16, 2 * s + selB);
                    ldsm4(bh[nt2], sbB + off);
                    ldsm4(bl[nt2], sbB + TILE_B + off);
                }
#pragma unroll
                for (int mt = 0; mt < 4; ++mt)
#pragma unroll
                    for (int nt = 0; nt < 4; ++nt) {
                        float* c = acc[mt][h * 4 + nt];
                        const u32* pbh = &bh[nt >> 1][(nt & 1) * 2];
                        const u32* pbl = &bl[nt >> 1][(nt & 1) * 2];
                        mma_bf16(c, ah[mt], pbh);
                        mma_bf16(c, al[mt], pbh);
                        mma_bf16(c, ah[mt], pbl);
                    }
            }
        }
        __syncthreads();
    }

    // epilogue: direct fp32 stores
#pragma unroll
    for (int mt = 0; mt < 4; ++mt) {
        const int r0 = row0 + wm + mt * 16 + (lane >> 2);
#pragma unroll
        for (int nt = 0; nt < 8; ++nt) {
            const int cc = col0 + wn + nt * 8 + (lane & 3) * 2;
            float* o0 = Cout + (size_t)r0 * 1024 + cc;
            float* o1 = Cout + (size_t)(r0 + 8) * 1024 + cc;
            o0[0] = acc[mt][nt][0]; o0[1] = acc[mt][nt][1];
            o1[0] = acc[mt][nt][2]; o1[1] = acc[mt][nt][3];
        }
    }
}

// ---------------------------------------------------------------------------
// Prep: split X into bf16 hi/lo
// ---------------------------------------------------------------------------
__global__ __launch_bounds__(256)
void gvq_split_kernel(const float* __restrict__ X, bf16* __restrict__ hi, bf16* __restrict__ lo)
{
    size_t i = (size_t)blockIdx.x * 256 + threadIdx.x;   // float4 index
    float4 v = reinterpret_cast<const float4*>(X)[i];
    bf16 h0, h1, h2, h3, l0, l1, l2, l3;
    split2(v.x, h0, l0); split2(v.y, h1, l1); split2(v.z, h2, l2); split2(v.w, h3, l3);
    __nv_bfloat162* H = reinterpret_cast<__nv_bfloat162*>(hi);
    __nv_bfloat162* L = reinterpret_cast<__nv_bfloat162*>(lo);
    H[2 * i]     = __nv_bfloat162(h0, h1);
    H[2 * i + 1] = __nv_bfloat162(h2, h3);
    L[2 * i]     = __nv_bfloat162(l0, l1);
    L[2 * i + 1] = __nv_bfloat162(l2, l3);
}

// ---------------------------------------------------------------------------
// Prep: split codebook (straight) + split transposed codebook
// ---------------------------------------------------------------------------
__global__ __launch_bounds__(256)
void gvq_splitC_kernel(const float* __restrict__ C)
{
    __shared__ float t[32][33];
    const int tx = threadIdx.x, ty = threadIdx.y;   // 32 x 8
    const int x = blockIdx.x * 32 + tx;
#pragma unroll
    for (int j = 0; j < 4; ++j) {
        int y = blockIdx.y * 32 + ty + j * 8;
        float v = C[(size_t)y * GVQ_D + x];
        t[ty + j * 8][tx] = v;
        bf16 h, l; split2(v, h, l);
        g_Chi[(size_t)y * GVQ_D + x] = h;
        g_Clo[(size_t)y * GVQ_D + x] = l;
    }
    __syncthreads();
    const int x2 = blockIdx.y * 32 + tx;
#pragma unroll
    for (int j = 0; j < 4; ++j) {
        int y2 = blockIdx.x * 32 + ty + j * 8;
        float v = t[tx][ty + j * 8];
        bf16 h, l; split2(v, h, l);
        g_CThi[(size_t)y2 * GVQ_V + x2] = h;
        g_CTlo[(size_t)y2 * GVQ_V + x2] = l;
    }
}

// ---------------------------------------------------------------------------
// Gumbel + softmax (in place) with fast intrinsics; emits bf16 hi/lo split too
// ---------------------------------------------------------------------------
__global__ __launch_bounds__(256)
void gvq_gumbel_softmax_kernel(float* __restrict__ S, const float* __restrict__ U,
                               bf16* __restrict__ Shi, bf16* __restrict__ Slo)
{
    const int row = blockIdx.x;
    float* s       = S + (size_t)row * GVQ_V;
    const float* u = U + (size_t)row * GVQ_V;
    const int tid  = threadIdx.x;
    const int lane = tid & 31;
    const int wid  = tid >> 5;

    __shared__ float red[8];
    __shared__ float stat;

    float z[4];
    float m = -CUDART_INF_F;
#pragma unroll
    for (int i = 0; i < 4; ++i) {
        int idx = tid + i * 256;
        float uu = u[idx];
        float g  = -__logf(-__logf(uu + 1e-20f) + 1e-20f);
        float zz = (s[idx] + g) * 2.0f;   // 1/TEMPERATURE
        z[i] = zz;
        m = fmaxf(m, zz);
    }
#pragma unroll
    for (int o = 16; o > 0; o >>= 1)
        m = fmaxf(m, __shfl_xor_sync(0xffffffffu, m, o));
    if (lane == 0) red[wid] = m;
    __syncthreads();
    if (tid == 0) {
        float mm = red[0];
#pragma unroll
        for (int i = 1; i < 8; ++i) mm = fmaxf(mm, red[i]);
        stat = mm;
    }
    __syncthreads();
    m = stat;

    float lsum = 0.0f;
#pragma unroll
    for (int i = 0; i < 4; ++i) {
        z[i] = __expf(z[i] - m);
        lsum += z[i];
    }
#pragma unroll
    for (int o = 16; o > 0; o >>= 1)
        lsum += __shfl_xor_sync(0xffffffffu, lsum, o);
    __syncthreads();
    if (lane == 0) red[wid] = lsum;
    __syncthreads();
    if (tid == 0) {
        float tsum = 0.0f;
#pragma unroll
        for (int i = 0; i < 8; ++i) tsum += red[i];
        stat = tsum;
    }
    __syncthreads();
    const float inv = 1.0f / stat;

#pragma unroll
    for (int i = 0; i < 4; ++i) {
        int idx = tid + i * 256;
        float p = z[i] * inv;
        s[idx] = p;
        bf16 h, l; split2(p, h, l);
        Shi[(size_t)row * GVQ_V + idx] = h;
        Slo[(size_t)row * GVQ_V + idx] = l;
    }
}

// ---------------------------------------------------------------------------
// kernel_launch
// ---------------------------------------------------------------------------
extern "C" void kernel_launch(void* const* d_in, const int* in_sizes, int n_in,
                              void* d_out, int out_size)
{
    (void)in_sizes; (void)n_in; (void)out_size;
    const float* X = (const float*)d_in[0];
    const float* C = (const float*)d_in[1];
    const float* U = (const float*)d_in[2];

    float* quant = (float*)d_out;                           // B*T*D
    float* soft  = (float*)d_out + (size_t)GVQ_M * GVQ_D;   // B*T*V

    void *pXhi, *pXlo, *pShi, *pSlo, *pChi, *pClo, *pCThi, *pCTlo;
    cudaGetSymbolAddress(&pXhi, g_Xhi);   cudaGetSymbolAddress(&pXlo, g_Xlo);
    cudaGetSymbolAddress(&pShi, g_Shi);   cudaGetSymbolAddress(&pSlo, g_Slo);
    cudaGetSymbolAddress(&pChi, g_Chi);   cudaGetSymbolAddress(&pClo, g_Clo);
    cudaGetSymbolAddress(&pCThi, g_CThi); cudaGetSymbolAddress(&pCTlo, g_CTlo);

    cudaFuncSetAttribute(gvq_mma_gemm, cudaFuncAttributeMaxDynamicSharedMemorySize, GVQ_SMEM);

    // 1) split X
    gvq_split_kernel<<<(GVQ_M * GVQ_D) / (256 * 4), 256>>>(X, (bf16*)pXhi, (bf16*)pXlo);
    // 2) split + transpose codebook
    gvq_splitC_kernel<<<dim3(32, 32), dim3(32, 8)>>>(C);
    // 3) logits = X @ C^T  -> soft region (fp32)
    gvq_mma_gemm<<<dim3(GVQ_V / 128, GVQ_M / 128), 128, GVQ_SMEM>>>(
        (const bf16*)pXhi, (const bf16*)pXlo, (const bf16*)pChi, (const bf16*)pClo, soft);
    // 4) gumbel softmax in place + bf16 split of result
    gvq_gumbel_softmax_kernel<<<GVQ_M, 256>>>(soft, U, (bf16*)pShi, (bf16*)pSlo);
    // 5) quantized = soft @ C  (B operand = C^T, K-major) -> quant region
    gvq_mma_gemm<<<dim3(GVQ_D / 128, GVQ_M / 128), 128, GVQ_SMEM>>>(
        (const bf16*)pShi, (const bf16*)pSlo, (const bf16*)pCThi, (const bf16*)pCTlo, quant);
}